// round 5
// baseline (speedup 1.0000x reference)
#include <cuda_runtime.h>
#include <math_constants.h>

#define BB    32
#define NN    512
#define DIN_  768
#define DOUT_ 256
#define MROWS (BB * NN)          // 16384
#define NEGV  (-9.0e15f)
#define SLOPE 0.2f

// Scratch (device globals: allocation-free)
__device__ float g_Wh[MROWS * DOUT_];   // 16 MB
__device__ float g_s1[MROWS];
__device__ float g_s2[MROWS];

// ---------------------------------------------------------------------------
// Kernel 1: Wh = h @ W + pos_table[positions]
// M=16384, K=768, N=256. Block tile 128x128, BK=8, 256 threads, 8x8 per
// thread, double-buffered smem with register prefetch.
// ---------------------------------------------------------------------------
__global__ __launch_bounds__(256, 2)
void gemm_wh_kernel(const float* __restrict__ h,
                    const float* __restrict__ W,
                    const int*   __restrict__ positions,
                    const float* __restrict__ pos_table) {
    __shared__ float As[2][8][132];   // [buf][k][m], padded
    __shared__ float Bs[2][8][132];   // [buf][k][n], padded

    const int tid = threadIdx.x;
    const int m0 = blockIdx.y * 128;
    const int n0 = blockIdx.x * 128;

    const int tx = tid & 15;          // n-direction (16)
    const int ty = tid >> 4;          // m-direction (16)

    // A load: thread -> (row = tid/2, k-seg = (tid&1)*4), float4 along k
    const int arow = tid >> 1;        // 0..127
    const int ak4  = (tid & 1) * 4;   // 0 or 4
    // B load: thread -> (k = tid/32, n-seg = (tid&31)*4), float4 along n
    const int bk   = tid >> 5;        // 0..7
    const int bn4  = (tid & 31) * 4;  // 0..124

    const float* hA = h + (size_t)(m0 + arow) * DIN_;

    float4 aR = *(const float4*)&hA[ak4];
    float4 bR = *(const float4*)&W[(size_t)bk * DOUT_ + n0 + bn4];

    float acc[8][8];
#pragma unroll
    for (int i = 0; i < 8; i++)
#pragma unroll
        for (int j = 0; j < 8; j++) acc[i][j] = 0.f;

    int buf = 0;
    const int NTILES = DIN_ / 8;      // 96
    for (int kt = 0; kt < NTILES; kt++) {
        As[buf][ak4 + 0][arow] = aR.x;
        As[buf][ak4 + 1][arow] = aR.y;
        As[buf][ak4 + 2][arow] = aR.z;
        As[buf][ak4 + 3][arow] = aR.w;
        *(float4*)&Bs[buf][bk][bn4] = bR;
        __syncthreads();

        if (kt + 1 < NTILES) {
            const int k0 = (kt + 1) * 8;
            aR = *(const float4*)&hA[k0 + ak4];
            bR = *(const float4*)&W[(size_t)(k0 + bk) * DOUT_ + n0 + bn4];
        }

#pragma unroll
        for (int k = 0; k < 8; k++) {
            float4 a0 = *(float4*)&As[buf][k][ty * 4];
            float4 a1 = *(float4*)&As[buf][k][ty * 4 + 64];
            float4 b0 = *(float4*)&Bs[buf][k][tx * 4];
            float4 b1 = *(float4*)&Bs[buf][k][tx * 4 + 64];
            float ar[8] = {a0.x, a0.y, a0.z, a0.w, a1.x, a1.y, a1.z, a1.w};
            float br[8] = {b0.x, b0.y, b0.z, b0.w, b1.x, b1.y, b1.z, b1.w};
#pragma unroll
            for (int i = 0; i < 8; i++)
#pragma unroll
                for (int j = 0; j < 8; j++)
                    acc[i][j] = fmaf(ar[i], br[j], acc[i][j]);
        }
        buf ^= 1;
    }

    // Epilogue: add pos_table[positions[row]] and store
#pragma unroll
    for (int ih = 0; ih < 2; ih++) {
#pragma unroll
        for (int i = 0; i < 4; i++) {
            const int row = m0 + ih * 64 + ty * 4 + i;
            const int pos = positions[row];
            const float* pt = &pos_table[(size_t)pos * DOUT_];
#pragma unroll
            for (int jh = 0; jh < 2; jh++) {
                const int col = n0 + jh * 64 + tx * 4;
                const float4 p = *(const float4*)&pt[col];
                float4 o;
                o.x = acc[ih * 4 + i][jh * 4 + 0] + p.x;
                o.y = acc[ih * 4 + i][jh * 4 + 1] + p.y;
                o.z = acc[ih * 4 + i][jh * 4 + 2] + p.z;
                o.w = acc[ih * 4 + i][jh * 4 + 3] + p.w;
                *(float4*)&g_Wh[(size_t)row * DOUT_ + col] = o;
            }
        }
    }
}

// ---------------------------------------------------------------------------
// Kernel 2: s1 = Wh . a1, s2 = Wh . a2 per row. One warp per row.
// ---------------------------------------------------------------------------
__global__ void s12_kernel(const float* __restrict__ a1,
                           const float* __restrict__ a2) {
    __shared__ float sa1[DOUT_], sa2[DOUT_];
    const int tid = threadIdx.x;
    sa1[tid] = a1[tid];
    sa2[tid] = a2[tid];
    __syncthreads();

    const int warp = tid >> 5, lane = tid & 31;
    const int row = blockIdx.x * 8 + warp;
    const float* wr = &g_Wh[(size_t)row * DOUT_];

    float p1 = 0.f, p2 = 0.f;
#pragma unroll
    for (int c = 0; c < 2; c++) {
        int idx = (c * 32 + lane) * 4;
        float4 v = *(const float4*)&wr[idx];
        p1 += v.x * sa1[idx] + v.y * sa1[idx + 1] + v.z * sa1[idx + 2] + v.w * sa1[idx + 3];
        p2 += v.x * sa2[idx] + v.y * sa2[idx + 1] + v.z * sa2[idx + 2] + v.w * sa2[idx + 3];
    }
#pragma unroll
    for (int o = 16; o; o >>= 1) {
        p1 += __shfl_xor_sync(0xFFFFFFFFu, p1, o);
        p2 += __shfl_xor_sync(0xFFFFFFFFu, p2, o);
    }
    if (lane == 0) {
        g_s1[row] = p1;
        g_s2[row] = p2;
    }
}

// ---------------------------------------------------------------------------
// Kernel 3: masked softmax attention + h_prime = att @ Wh.
// One block per (batch b, tile of 32 i-rows). 256 threads.
// Dynamic smem: att[32][512] (64KB) + s2[512] (2KB).
// ---------------------------------------------------------------------------
extern __shared__ float smem3[];

__global__ void attn_kernel(const int* __restrict__ adj,
                            float* __restrict__ out_h,
                            float* __restrict__ out_att) {
    float* s_att = smem3;              // 32 * 512
    float* s_s2  = smem3 + 32 * NN;    // 512

    const int tid = threadIdx.x;
    const int blk = blockIdx.x;
    const int b  = blk >> 4;           // 16 tiles per batch
    const int it = blk & 15;

    s_s2[tid]       = g_s2[b * NN + tid];
    s_s2[tid + 256] = g_s2[b * NN + tid + 256];
    __syncthreads();

    const int warp = tid >> 5, lane = tid & 31;

    // Phase A: per-row masked leaky-relu softmax; each warp does 4 rows.
    // Row kept in registers (4 x float4 per lane) across all 3 passes.
    for (int r = 0; r < 4; r++) {
        const int li = warp * 4 + r;           // 0..31
        const int grow = b * NN + it * 32 + li;
        const float s1i = g_s1[grow];
        const int4* arow4 = (const int4*)&adj[(size_t)grow * NN];
        float4* att_row4 = (float4*)&s_att[li * NN];
        float4* gatt4 = (float4*)&out_att[(size_t)grow * NN];

        float4 v[4];
        float m = -CUDART_INF_F;
#pragma unroll
        for (int c = 0; c < 4; c++) {
            const int j = c * 32 + lane;       // float4 index
            const int4  av  = arow4[j];
            const float4 s2v = *(const float4*)&s_s2[j * 4];
            float4 e;
            e.x = s1i + s2v.x; e.x = e.x > 0.f ? e.x : SLOPE * e.x;
            e.y = s1i + s2v.y; e.y = e.y > 0.f ? e.y : SLOPE * e.y;
            e.z = s1i + s2v.z; e.z = e.z > 0.f ? e.z : SLOPE * e.z;
            e.w = s1i + s2v.w; e.w = e.w > 0.f ? e.w : SLOPE * e.w;
            e.x = (av.x > 0) ? e.x : NEGV;
            e.y = (av.y > 0) ? e.y : NEGV;
            e.z = (av.z > 0) ? e.z : NEGV;
            e.w = (av.w > 0) ? e.w : NEGV;
            v[c] = e;
            m = fmaxf(m, fmaxf(fmaxf(e.x, e.y), fmaxf(e.z, e.w)));
        }
#pragma unroll
        for (int o = 16; o; o >>= 1) m = fmaxf(m, __shfl_xor_sync(0xFFFFFFFFu, m, o));

        float s = 0.f;
#pragma unroll
        for (int c = 0; c < 4; c++) {
            v[c].x = __expf(v[c].x - m);
            v[c].y = __expf(v[c].y - m);
            v[c].z = __expf(v[c].z - m);
            v[c].w = __expf(v[c].w - m);
            s += (v[c].x + v[c].y) + (v[c].z + v[c].w);
        }
#pragma unroll
        for (int o = 16; o; o >>= 1) s += __shfl_xor_sync(0xFFFFFFFFu, s, o);
        const float rinv = 1.f / s;

#pragma unroll
        for (int c = 0; c < 4; c++) {
            const int j = c * 32 + lane;
            float4 p;
            p.x = v[c].x * rinv;
            p.y = v[c].y * rinv;
            p.z = v[c].z * rinv;
            p.w = v[c].w * rinv;
            att_row4[j] = p;
            gatt4[j] = p;
        }
    }
    __syncthreads();

    // Phase B: h_prime tile [32 x 256] = att [32 x 512] @ Wh_b [512 x 256].
    // Split: threads 0-127 -> rows 0-15, threads 128-255 -> rows 16-31.
    // Each thread owns dims d and d+128 for its 16 rows (32 accumulators).
    const int half = tid >> 7;         // 0 or 1
    const int d    = tid & 127;
    const int r0   = half * 16;

    float acc0[16], acc1[16];
#pragma unroll
    for (int i = 0; i < 16; i++) { acc0[i] = 0.f; acc1[i] = 0.f; }

    const float* whb = &g_Wh[(size_t)b * NN * DOUT_ + d];
    for (int j4 = 0; j4 < NN / 4; j4++) {
        const int j = j4 * 4;
        const float w00 = whb[(size_t)(j + 0) * DOUT_];
        const float w01 = whb[(size_t)(j + 0) * DOUT_ + 128];
        const float w10 = whb[(size_t)(j + 1) * DOUT_];
        const float w11 = whb[(size_t)(j + 1) * DOUT_ + 128];
        const float w20 = whb[(size_t)(j + 2) * DOUT_];
        const float w21 = whb[(size_t)(j + 2) * DOUT_ + 128];
        const float w30 = whb[(size_t)(j + 3) * DOUT_];
        const float w31 = whb[(size_t)(j + 3) * DOUT_ + 128];
#pragma unroll
        for (int i = 0; i < 16; i++) {
            const float4 a = *(float4*)&s_att[(r0 + i) * NN + j];
            acc0[i] = fmaf(a.x, w00, acc0[i]);
            acc0[i] = fmaf(a.y, w10, acc0[i]);
            acc0[i] = fmaf(a.z, w20, acc0[i]);
            acc0[i] = fmaf(a.w, w30, acc0[i]);
            acc1[i] = fmaf(a.x, w01, acc1[i]);
            acc1[i] = fmaf(a.y, w11, acc1[i]);
            acc1[i] = fmaf(a.z, w21, acc1[i]);
            acc1[i] = fmaf(a.w, w31, acc1[i]);
        }
    }

    const int ibase = it * 32 + r0;
#pragma unroll
    for (int i = 0; i < 16; i++) {
        float* orow = &out_h[(size_t)(b * NN + ibase + i) * DOUT_];
        orow[d]       = acc0[i];
        orow[d + 128] = acc1[i];
    }
}

// ---------------------------------------------------------------------------
extern "C" void kernel_launch(void* const* d_in, const int* in_sizes, int n_in,
                              void* d_out, int out_size) {
    const float* h         = (const float*)d_in[0];
    const int*   adj       = (const int*)  d_in[1];
    const int*   positions = (const int*)  d_in[2];
    const float* W         = (const float*)d_in[3];
    const float* a1        = (const float*)d_in[4];
    const float* a2        = (const float*)d_in[5];
    const float* pos_table = (const float*)d_in[6];

    float* out_h   = (float*)d_out;                           // [32,512,256]
    float* out_att = (float*)d_out + (size_t)BB * NN * DOUT_; // [32,512,512]

    dim3 g1(DOUT_ / 128, MROWS / 128);
    gemm_wh_kernel<<<g1, 256>>>(h, W, positions, pos_table);

    s12_kernel<<<MROWS / 8, 256>>>(a1, a2);

    const int smem3_sz = (32 * NN + NN) * (int)sizeof(float);  // 67584 B
    cudaFuncSetAttribute(attn_kernel, cudaFuncAttributeMaxDynamicSharedMemorySize,
                         smem3_sz);
    attn_kernel<<<BB * 16, 256, smem3_sz>>>(adj, out_h, out_att);
}

// round 10
// speedup vs baseline: 1.9165x; 1.9165x over previous
#include <cuda_runtime.h>
#include <cuda_bf16.h>
#include <math_constants.h>
#include <cstdint>

#define BB    32
#define NN    512
#define DIN_  768
#define DOUT_ 256
#define MROWS (BB * NN)          // 16384
#define NEGV  (-9.0e15f)
#define SLOPE 0.2f

// Scratch (device globals: allocation-free)
__device__ float g_Wh[MROWS * DOUT_];   // 16 MB
__device__ float g_s1[MROWS];
__device__ float g_s2[MROWS];
// W transposed + bf16-split: [DOUT_=256 rows][DIN_=768 cols], K-major
__device__ __nv_bfloat16 g_WT_hi[DOUT_ * DIN_];
__device__ __nv_bfloat16 g_WT_lo[DOUT_ * DIN_];

// ---------------------------------------------------------------------------
// Helpers (all plain sm_103 features: mma.sync, ldmatrix, cp.async)
// ---------------------------------------------------------------------------
__device__ __forceinline__ uint32_t smem_u32(const void* p) {
    uint32_t a;
    asm("{ .reg .u64 t; cvta.to.shared.u64 t, %1; cvt.u32.u64 %0, t; }"
        : "=r"(a) : "l"(p));
    return a;
}

#define LDSM_X4(r, addr)                                                      \
    asm volatile("ldmatrix.sync.aligned.m8n8.x4.shared.b16 {%0,%1,%2,%3}, [%4];" \
                 : "=r"((r)[0]), "=r"((r)[1]), "=r"((r)[2]), "=r"((r)[3])     \
                 : "r"(addr))

__device__ __forceinline__ void mma16816(float* c, const uint32_t* a,
                                         uint32_t b0, uint32_t b1) {
    asm volatile(
        "mma.sync.aligned.m16n8k16.row.col.f32.bf16.bf16.f32 "
        "{%0,%1,%2,%3}, {%4,%5,%6,%7}, {%8,%9}, {%0,%1,%2,%3};"
        : "+f"(c[0]), "+f"(c[1]), "+f"(c[2]), "+f"(c[3])
        : "r"(a[0]), "r"(a[1]), "r"(a[2]), "r"(a[3]), "r"(b0), "r"(b1));
}

#define CP_ASYNC16(dst, src) \
    asm volatile("cp.async.cg.shared.global [%0], [%1], 16;" :: "r"(dst), "l"(src))
#define CP_COMMIT()  asm volatile("cp.async.commit_group;" ::: "memory")
#define CP_WAIT0()   asm volatile("cp.async.wait_group 0;" ::: "memory")

__device__ __forceinline__ uint32_t pack_bf2(__nv_bfloat16 a, __nv_bfloat16 b) {
    __nv_bfloat162 t(a, b);
    return *(uint32_t*)&t;
}

// ---------------------------------------------------------------------------
// Kernel 0: W [768,256] fp32  ->  W^T hi/lo bf16  [256,768]
// ---------------------------------------------------------------------------
__global__ void wt_convert_kernel(const float* __restrict__ W) {
    const int idx = blockIdx.x * 256 + threadIdx.x;   // 0..49151
    const int k  = idx >> 6;                          // 0..767
    const int n4 = (idx & 63) * 4;                    // 0..252
    const float4 v = *(const float4*)&W[(size_t)k * DOUT_ + n4];
    const float vv[4] = {v.x, v.y, v.z, v.w};
#pragma unroll
    for (int j = 0; j < 4; j++) {
        __nv_bfloat16 hi = __float2bfloat16(vv[j]);
        __nv_bfloat16 lo = __float2bfloat16(vv[j] - __bfloat162float(hi));
        g_WT_hi[(size_t)(n4 + j) * DIN_ + k] = hi;
        g_WT_lo[(size_t)(n4 + j) * DIN_ + k] = lo;
    }
}

// ---------------------------------------------------------------------------
// Kernel 1: Wh = h @ W + pos_table[positions]
// mma.sync bf16 3-term split GEMM. Block tile 128x128, 8 warps (4m x 2n),
// warp tile 32x64, K-chunk 32, double-buffered smem, cp.async for B.
//
// smem byte layout per buffer (stride 40 bf16 = 80 B rows, conflict-free for
// both ldmatrix (5x16B mod 8 covers all banks) and 8B stores):
//   AH: +0      (128 rows x 40)  10240 B
//   AL: +10240
//   BH: +20480
//   BL: +30720
// buffer stride 40960 B, total 81920 B dynamic.
// ---------------------------------------------------------------------------
#define PAD    40
#define CHUNK  32
#define NCHK   (DIN_ / CHUNK)     // 24
#define BUF_B  40960
#define GSMEM  (2 * BUF_B)

extern __shared__ char smem_g[];

__device__ __forceinline__ void load_A_regs(const float* __restrict__ h,
                                            int m0, int kbase, int tid,
                                            float4* aR) {
#pragma unroll
    for (int i = 0; i < 4; i++) {
        const int e = tid + i * 256;          // 0..1023
        const int row = e >> 3;               // 0..127
        const int c4  = (e & 7) * 4;          // 0..28
        aR[i] = *(const float4*)&h[(size_t)(m0 + row) * DIN_ + kbase + c4];
    }
}

__device__ __forceinline__ void store_A_smem(char* s, int tid, const float4* aR) {
#pragma unroll
    for (int i = 0; i < 4; i++) {
        const int e = tid + i * 256;
        const int row = e >> 3;
        const int c4  = (e & 7) * 4;
        const float4 v = aR[i];
        __nv_bfloat16 hx = __float2bfloat16(v.x);
        __nv_bfloat16 hy = __float2bfloat16(v.y);
        __nv_bfloat16 hz = __float2bfloat16(v.z);
        __nv_bfloat16 hw = __float2bfloat16(v.w);
        __nv_bfloat16 lx = __float2bfloat16(v.x - __bfloat162float(hx));
        __nv_bfloat16 ly = __float2bfloat16(v.y - __bfloat162float(hy));
        __nv_bfloat16 lz = __float2bfloat16(v.z - __bfloat162float(hz));
        __nv_bfloat16 lw = __float2bfloat16(v.w - __bfloat162float(hw));
        const uint32_t bo = (uint32_t)(row * (PAD * 2) + c4 * 2);   // bytes
        uint2 hv; hv.x = pack_bf2(hx, hy); hv.y = pack_bf2(hz, hw);
        uint2 lv; lv.x = pack_bf2(lx, ly); lv.y = pack_bf2(lz, lw);
        *(uint2*)(s + bo)         = hv;          // AH
        *(uint2*)(s + 10240 + bo) = lv;          // AL
    }
}

__device__ __forceinline__ void cpasync_B(uint32_t bh_byte, int n0, int kbase,
                                          int tid) {
#pragma unroll
    for (int i = 0; i < 2; i++) {
        const int e = tid + i * 256;          // 0..511
        const int row = e >> 2;               // 0..127
        const int q   = e & 3;                // 0..3
        const size_t gi = (size_t)(n0 + row) * DIN_ + kbase + q * 8;
        const uint32_t d = bh_byte + (uint32_t)(row * (PAD * 2) + q * 16);
        CP_ASYNC16(d,         (const void*)&g_WT_hi[gi]);
        CP_ASYNC16(d + 10240, (const void*)&g_WT_lo[gi]);
    }
}

__global__ __launch_bounds__(256, 2)
void gemm_wh_mma_kernel(const float* __restrict__ h,
                        const int*   __restrict__ positions,
                        const float* __restrict__ pos_table) {
    const uint32_t sb = smem_u32(smem_g);
    const int tid  = threadIdx.x;
    const int wid  = tid >> 5;
    const int lane = tid & 31;
    const int wm = wid >> 1;           // 0..3
    const int wn = wid & 1;            // 0..1
    const int m0 = blockIdx.y * 128;
    const int n0 = blockIdx.x * 128;

    // ldmatrix per-lane offsets
    const int lr = lane & 15;                         // A row in m16 tile
    const int lk = (lane >> 4) * 8;                   // A k-half
    const int bn = ((lane >> 4) * 8) + (lane & 7);    // B n within 16-group
    const int bk = ((lane >> 3) & 1) * 8;             // B k-half

    float acc[2][8][4];
#pragma unroll
    for (int mi = 0; mi < 2; mi++)
#pragma unroll
        for (int ni = 0; ni < 8; ni++)
#pragma unroll
            for (int q = 0; q < 4; q++) acc[mi][ni][q] = 0.f;

    float4 aR[4];

    // Prologue: chunk 0
    cpasync_B(sb + 20480, n0, 0, tid);
    CP_COMMIT();
    load_A_regs(h, m0, 0, tid, aR);
    store_A_smem(smem_g, tid, aR);
    CP_WAIT0();
    __syncthreads();

    for (int c = 0; c < NCHK; c++) {
        const int buf  = c & 1;
        const int nbuf = buf ^ 1;

        if (c < NCHK - 1) {
            const int kn = (c + 1) * CHUNK;
            cpasync_B(sb + nbuf * BUF_B + 20480, n0, kn, tid);
            CP_COMMIT();
            load_A_regs(h, m0, kn, tid, aR);
        }

        const uint32_t AH = sb + buf * BUF_B;
        const uint32_t BH = AH + 20480;

#pragma unroll
        for (int k16 = 0; k16 < CHUNK; k16 += 16) {
            uint32_t ah[2][4], al[2][4];
#pragma unroll
            for (int mi = 0; mi < 2; mi++) {
                const uint32_t aa =
                    AH + (uint32_t)(((wm * 32 + mi * 16 + lr) * PAD + k16 + lk) * 2);
                LDSM_X4(ah[mi], aa);
                LDSM_X4(al[mi], aa + 10240);
            }
#pragma unroll
            for (int g = 0; g < 4; g++) {
                const uint32_t ba =
                    BH + (uint32_t)(((wn * 64 + g * 16 + bn) * PAD + k16 + bk) * 2);
                uint32_t bh[4], bl[4];
                LDSM_X4(bh, ba);
                LDSM_X4(bl, ba + 10240);
#pragma unroll
                for (int mi = 0; mi < 2; mi++) {
                    mma16816(acc[mi][2 * g],     ah[mi], bh[0], bh[1]);
                    mma16816(acc[mi][2 * g + 1], ah[mi], bh[2], bh[3]);
                    mma16816(acc[mi][2 * g],     al[mi], bh[0], bh[1]);
                    mma16816(acc[mi][2 * g + 1], al[mi], bh[2], bh[3]);
                    mma16816(acc[mi][2 * g],     ah[mi], bl[0], bl[1]);
                    mma16816(acc[mi][2 * g + 1], ah[mi], bl[2], bl[3]);
                }
            }
        }

        if (c < NCHK - 1) store_A_smem(smem_g + nbuf * BUF_B, tid, aR);
        CP_WAIT0();
        __syncthreads();
    }

    // Epilogue: C frag (c0,c1)=row g, (c2,c3)=row g+8; cols 2t,2t+1.
    const int g = lane >> 2, t = lane & 3;
#pragma unroll
    for (int mi = 0; mi < 2; mi++) {
#pragma unroll
        for (int h2 = 0; h2 < 2; h2++) {
            const int row = m0 + wm * 32 + mi * 16 + g + h2 * 8;
            const int pos = positions[row];
            const float* pt = &pos_table[(size_t)pos * DOUT_];
            float* orow = &g_Wh[(size_t)row * DOUT_];
#pragma unroll
            for (int ni = 0; ni < 8; ni++) {
                const int col = n0 + wn * 64 + ni * 8 + t * 2;
                const float2 p = *(const float2*)&pt[col];
                float2 o;
                o.x = acc[mi][ni][h2 * 2 + 0] + p.x;
                o.y = acc[mi][ni][h2 * 2 + 1] + p.y;
                *(float2*)&orow[col] = o;
            }
        }
    }
}

// ---------------------------------------------------------------------------
// Kernel 2: s1 = Wh . a1, s2 = Wh . a2 per row. One warp per row.
// ---------------------------------------------------------------------------
__global__ void s12_kernel(const float* __restrict__ a1,
                           const float* __restrict__ a2) {
    __shared__ float sa1[DOUT_], sa2[DOUT_];
    const int tid = threadIdx.x;
    sa1[tid] = a1[tid];
    sa2[tid] = a2[tid];
    __syncthreads();

    const int warp = tid >> 5, lane = tid & 31;
    const int row = blockIdx.x * 8 + warp;
    const float* wr = &g_Wh[(size_t)row * DOUT_];

    float p1 = 0.f, p2 = 0.f;
#pragma unroll
    for (int c = 0; c < 2; c++) {
        int idx = (c * 32 + lane) * 4;
        float4 v = *(const float4*)&wr[idx];
        p1 += v.x * sa1[idx] + v.y * sa1[idx + 1] + v.z * sa1[idx + 2] + v.w * sa1[idx + 3];
        p2 += v.x * sa2[idx] + v.y * sa2[idx + 1] + v.z * sa2[idx + 2] + v.w * sa2[idx + 3];
    }
#pragma unroll
    for (int o = 16; o; o >>= 1) {
        p1 += __shfl_xor_sync(0xFFFFFFFFu, p1, o);
        p2 += __shfl_xor_sync(0xFFFFFFFFu, p2, o);
    }
    if (lane == 0) {
        g_s1[row] = p1;
        g_s2[row] = p2;
    }
}

// ---------------------------------------------------------------------------
// Kernel 3: masked softmax attention + h_prime = att @ Wh.  (R1 version)
// One block per (batch b, tile of 32 i-rows). 256 threads.
// Dynamic smem: att[32][512] (64KB) + s2[512] (2KB).
// ---------------------------------------------------------------------------
extern __shared__ float smem3[];

__global__ void attn_kernel(const int* __restrict__ adj,
                            float* __restrict__ out_h,
                            float* __restrict__ out_att) {
    float* s_att = smem3;              // 32 * 512
    float* s_s2  = smem3 + 32 * NN;    // 512

    const int tid = threadIdx.x;
    const int blk = blockIdx.x;
    const int b  = blk >> 4;           // 16 tiles per batch
    const int it = blk & 15;

    s_s2[tid]       = g_s2[b * NN + tid];
    s_s2[tid + 256] = g_s2[b * NN + tid + 256];
    __syncthreads();

    const int warp = tid >> 5, lane = tid & 31;

    // Phase A: per-row masked leaky-relu softmax; each warp does 4 rows.
    for (int r = 0; r < 4; r++) {
        const int li = warp * 4 + r;           // 0..31
        const int ii = it * 32 + li;
        const int grow = b * NN + ii;
        const float s1i = g_s1[grow];
        const int* arow = &adj[(size_t)grow * NN];
        float* att_row = &s_att[li * NN];

        float m = -CUDART_INF_F;
#pragma unroll
        for (int jj = 0; jj < 16; jj++) {
            int j = jj * 32 + lane;
            float e = s1i + s_s2[j];
            e = e > 0.f ? e : SLOPE * e;
            float v = (arow[j] > 0) ? e : NEGV;
            att_row[j] = v;
            m = fmaxf(m, v);
        }
#pragma unroll
        for (int o = 16; o; o >>= 1) m = fmaxf(m, __shfl_xor_sync(0xFFFFFFFFu, m, o));

        float s = 0.f;
#pragma unroll
        for (int jj = 0; jj < 16; jj++) {
            int j = jj * 32 + lane;
            float p = __expf(att_row[j] - m);
            att_row[j] = p;
            s += p;
        }
#pragma unroll
        for (int o = 16; o; o >>= 1) s += __shfl_xor_sync(0xFFFFFFFFu, s, o);
        const float rinv = 1.f / s;

        float* gatt = &out_att[(size_t)grow * NN];
#pragma unroll
        for (int jj = 0; jj < 16; jj++) {
            int j = jj * 32 + lane;
            float p = att_row[j] * rinv;
            att_row[j] = p;
            gatt[j] = p;
        }
    }
    __syncthreads();

    // Phase B: h_prime tile [32 x 256] = att [32 x 512] @ Wh_b [512 x 256].
    const int d = tid;
    float acc[32];
#pragma unroll
    for (int i = 0; i < 32; i++) acc[i] = 0.f;

    const float* whb = &g_Wh[(size_t)b * NN * DOUT_ + d];
    for (int j4 = 0; j4 < NN / 4; j4++) {
        float w0 = whb[(size_t)(j4 * 4 + 0) * DOUT_];
        float w1 = whb[(size_t)(j4 * 4 + 1) * DOUT_];
        float w2 = whb[(size_t)(j4 * 4 + 2) * DOUT_];
        float w3 = whb[(size_t)(j4 * 4 + 3) * DOUT_];
#pragma unroll
        for (int i = 0; i < 32; i++) {
            float4 a = *(float4*)&s_att[i * NN + j4 * 4];
            acc[i] = fmaf(a.x, w0, acc[i]);
            acc[i] = fmaf(a.y, w1, acc[i]);
            acc[i] = fmaf(a.z, w2, acc[i]);
            acc[i] = fmaf(a.w, w3, acc[i]);
        }
    }

    const int ibase = it * 32;
#pragma unroll
    for (int i = 0; i < 32; i++)
        out_h[(size_t)(b * NN + ibase + i) * DOUT_ + d] = acc[i];
}

// ---------------------------------------------------------------------------
extern "C" void kernel_launch(void* const* d_in, const int* in_sizes, int n_in,
                              void* d_out, int out_size) {
    const float* h         = (const float*)d_in[0];
    const int*   adj       = (const int*)  d_in[1];
    const int*   positions = (const int*)  d_in[2];
    const float* W         = (const float*)d_in[3];
    const float* a1        = (const float*)d_in[4];
    const float* a2        = (const float*)d_in[5];
    const float* pos_table = (const float*)d_in[6];

    float* out_h   = (float*)d_out;                           // [32,512,256]
    float* out_att = (float*)d_out + (size_t)BB * NN * DOUT_; // [32,512,512]

    wt_convert_kernel<<<192, 256>>>(W);

    cudaFuncSetAttribute(gemm_wh_mma_kernel,
                         cudaFuncAttributeMaxDynamicSharedMemorySize, GSMEM);
    dim3 g1(DOUT_ / 128, MROWS / 128);   // (2, 128) = 256 CTAs
    gemm_wh_mma_kernel<<<g1, 256, GSMEM>>>(h, positions, pos_table);

    s12_kernel<<<MROWS / 8, 256>>>(a1, a2);

    const int smem3_sz = (32 * NN + NN) * (int)sizeof(float);  // 67584 B
    cudaFuncSetAttribute(attn_kernel, cudaFuncAttributeMaxDynamicSharedMemorySize,
                         smem3_sz);
    attn_kernel<<<BB * 16, 256, smem3_sz>>>(adj, out_h, out_att);
}

// round 11
// speedup vs baseline: 3.2741x; 1.7084x over previous
#include <cuda_runtime.h>
#include <cuda_bf16.h>
#include <math_constants.h>
#include <cstdint>

#define BB    32
#define NN    512
#define DIN_  768
#define DOUT_ 256
#define MROWS (BB * NN)          // 16384
#define NEGV  (-9.0e15f)
#define SLOPE 0.2f

// Scratch (device globals: allocation-free)
__device__ float g_Wh[MROWS * DOUT_];   // 16 MB
__device__ float g_s1[MROWS];
__device__ float g_s2[MROWS];
// W transposed + bf16-split: [DOUT_=256 rows][DIN_=768 cols], K-major
__device__ __nv_bfloat16 g_WT_hi[DOUT_ * DIN_];
__device__ __nv_bfloat16 g_WT_lo[DOUT_ * DIN_];
// Wh bf16-split, same layout as g_Wh ([row][d]), for attn Phase-B MMA
__device__ __nv_bfloat16 g_Whbf_hi[MROWS * DOUT_];  // 8 MB
__device__ __nv_bfloat16 g_Whbf_lo[MROWS * DOUT_];  // 8 MB

// ---------------------------------------------------------------------------
// Helpers (plain sm_103 features: mma.sync, ldmatrix, cp.async)
// ---------------------------------------------------------------------------
__device__ __forceinline__ uint32_t smem_u32(const void* p) {
    uint32_t a;
    asm("{ .reg .u64 t; cvta.to.shared.u64 t, %1; cvt.u32.u64 %0, t; }"
        : "=r"(a) : "l"(p));
    return a;
}

#define LDSM_X4(r, addr)                                                      \
    asm volatile("ldmatrix.sync.aligned.m8n8.x4.shared.b16 {%0,%1,%2,%3}, [%4];" \
                 : "=r"((r)[0]), "=r"((r)[1]), "=r"((r)[2]), "=r"((r)[3])     \
                 : "r"(addr))
#define LDSM_X4_T(r, addr)                                                    \
    asm volatile("ldmatrix.sync.aligned.m8n8.x4.trans.shared.b16 {%0,%1,%2,%3}, [%4];" \
                 : "=r"((r)[0]), "=r"((r)[1]), "=r"((r)[2]), "=r"((r)[3])     \
                 : "r"(addr))

__device__ __forceinline__ void mma16816(float* c, const uint32_t* a,
                                         uint32_t b0, uint32_t b1) {
    asm volatile(
        "mma.sync.aligned.m16n8k16.row.col.f32.bf16.bf16.f32 "
        "{%0,%1,%2,%3}, {%4,%5,%6,%7}, {%8,%9}, {%0,%1,%2,%3};"
        : "+f"(c[0]), "+f"(c[1]), "+f"(c[2]), "+f"(c[3])
        : "r"(a[0]), "r"(a[1]), "r"(a[2]), "r"(a[3]), "r"(b0), "r"(b1));
}

#define CP_ASYNC16(dst, src) \
    asm volatile("cp.async.cg.shared.global [%0], [%1], 16;" :: "r"(dst), "l"(src))
#define CP_COMMIT()  asm volatile("cp.async.commit_group;" ::: "memory")
#define CP_WAIT0()   asm volatile("cp.async.wait_group 0;" ::: "memory")
#define CP_WAIT1()   asm volatile("cp.async.wait_group 1;" ::: "memory")

__device__ __forceinline__ uint32_t pack_bf2(__nv_bfloat16 a, __nv_bfloat16 b) {
    __nv_bfloat162 t(a, b);
    return *(uint32_t*)&t;
}

// ---------------------------------------------------------------------------
// Kernel 0: W [768,256] fp32  ->  W^T hi/lo bf16  [256,768]
// ---------------------------------------------------------------------------
__global__ void wt_convert_kernel(const float* __restrict__ W) {
    const int idx = blockIdx.x * 256 + threadIdx.x;   // 0..49151
    const int k  = idx >> 6;                          // 0..767
    const int n4 = (idx & 63) * 4;                    // 0..252
    const float4 v = *(const float4*)&W[(size_t)k * DOUT_ + n4];
    const float vv[4] = {v.x, v.y, v.z, v.w};
#pragma unroll
    for (int j = 0; j < 4; j++) {
        __nv_bfloat16 hi = __float2bfloat16(vv[j]);
        __nv_bfloat16 lo = __float2bfloat16(vv[j] - __bfloat162float(hi));
        g_WT_hi[(size_t)(n4 + j) * DIN_ + k] = hi;
        g_WT_lo[(size_t)(n4 + j) * DIN_ + k] = lo;
    }
}

// ---------------------------------------------------------------------------
// Kernel 1: Wh = h @ W + pos_table[positions]
// mma.sync bf16 3-term split GEMM. Block tile 128x128, 8 warps (4m x 2n),
// warp tile 32x64, K-chunk 32, double-buffered smem, cp.async for B.
// Epilogue also emits Wh as bf16 hi/lo for the attn Phase-B MMA.
// ---------------------------------------------------------------------------
#define PAD    40
#define CHUNK  32
#define NCHK   (DIN_ / CHUNK)     // 24
#define BUF_B  40960
#define GSMEM  (2 * BUF_B)

extern __shared__ char smem_g[];

__device__ __forceinline__ void load_A_regs(const float* __restrict__ h,
                                            int m0, int kbase, int tid,
                                            float4* aR) {
#pragma unroll
    for (int i = 0; i < 4; i++) {
        const int e = tid + i * 256;          // 0..1023
        const int row = e >> 3;               // 0..127
        const int c4  = (e & 7) * 4;          // 0..28
        aR[i] = *(const float4*)&h[(size_t)(m0 + row) * DIN_ + kbase + c4];
    }
}

__device__ __forceinline__ void store_A_smem(char* s, int tid, const float4* aR) {
#pragma unroll
    for (int i = 0; i < 4; i++) {
        const int e = tid + i * 256;
        const int row = e >> 3;
        const int c4  = (e & 7) * 4;
        const float4 v = aR[i];
        __nv_bfloat16 hx = __float2bfloat16(v.x);
        __nv_bfloat16 hy = __float2bfloat16(v.y);
        __nv_bfloat16 hz = __float2bfloat16(v.z);
        __nv_bfloat16 hw = __float2bfloat16(v.w);
        __nv_bfloat16 lx = __float2bfloat16(v.x - __bfloat162float(hx));
        __nv_bfloat16 ly = __float2bfloat16(v.y - __bfloat162float(hy));
        __nv_bfloat16 lz = __float2bfloat16(v.z - __bfloat162float(hz));
        __nv_bfloat16 lw = __float2bfloat16(v.w - __bfloat162float(hw));
        const uint32_t bo = (uint32_t)(row * (PAD * 2) + c4 * 2);   // bytes
        uint2 hv; hv.x = pack_bf2(hx, hy); hv.y = pack_bf2(hz, hw);
        uint2 lv; lv.x = pack_bf2(lx, ly); lv.y = pack_bf2(lz, lw);
        *(uint2*)(s + bo)         = hv;          // AH
        *(uint2*)(s + 10240 + bo) = lv;          // AL
    }
}

__device__ __forceinline__ void cpasync_B(uint32_t bh_byte, int n0, int kbase,
                                          int tid) {
#pragma unroll
    for (int i = 0; i < 2; i++) {
        const int e = tid + i * 256;          // 0..511
        const int row = e >> 2;               // 0..127
        const int q   = e & 3;                // 0..3
        const size_t gi = (size_t)(n0 + row) * DIN_ + kbase + q * 8;
        const uint32_t d = bh_byte + (uint32_t)(row * (PAD * 2) + q * 16);
        CP_ASYNC16(d,         (const void*)&g_WT_hi[gi]);
        CP_ASYNC16(d + 10240, (const void*)&g_WT_lo[gi]);
    }
}

__global__ __launch_bounds__(256, 2)
void gemm_wh_mma_kernel(const float* __restrict__ h,
                        const int*   __restrict__ positions,
                        const float* __restrict__ pos_table) {
    const uint32_t sb = smem_u32(smem_g);
    const int tid  = threadIdx.x;
    const int wid  = tid >> 5;
    const int lane = tid & 31;
    const int wm = wid >> 1;           // 0..3
    const int wn = wid & 1;            // 0..1
    const int m0 = blockIdx.y * 128;
    const int n0 = blockIdx.x * 128;

    const int lr = lane & 15;
    const int lk = (lane >> 4) * 8;
    const int bn = ((lane >> 4) * 8) + (lane & 7);
    const int bk = ((lane >> 3) & 1) * 8;

    float acc[2][8][4];
#pragma unroll
    for (int mi = 0; mi < 2; mi++)
#pragma unroll
        for (int ni = 0; ni < 8; ni++)
#pragma unroll
            for (int q = 0; q < 4; q++) acc[mi][ni][q] = 0.f;

    float4 aR[4];

    cpasync_B(sb + 20480, n0, 0, tid);
    CP_COMMIT();
    load_A_regs(h, m0, 0, tid, aR);
    store_A_smem(smem_g, tid, aR);
    CP_WAIT0();
    __syncthreads();

    for (int c = 0; c < NCHK; c++) {
        const int buf  = c & 1;
        const int nbuf = buf ^ 1;

        if (c < NCHK - 1) {
            const int kn = (c + 1) * CHUNK;
            cpasync_B(sb + nbuf * BUF_B + 20480, n0, kn, tid);
            CP_COMMIT();
            load_A_regs(h, m0, kn, tid, aR);
        }

        const uint32_t AH = sb + buf * BUF_B;
        const uint32_t BH = AH + 20480;

#pragma unroll
        for (int k16 = 0; k16 < CHUNK; k16 += 16) {
            uint32_t ah[2][4], al[2][4];
#pragma unroll
            for (int mi = 0; mi < 2; mi++) {
                const uint32_t aa =
                    AH + (uint32_t)(((wm * 32 + mi * 16 + lr) * PAD + k16 + lk) * 2);
                LDSM_X4(ah[mi], aa);
                LDSM_X4(al[mi], aa + 10240);
            }
#pragma unroll
            for (int g = 0; g < 4; g++) {
                const uint32_t ba =
                    BH + (uint32_t)(((wn * 64 + g * 16 + bn) * PAD + k16 + bk) * 2);
                uint32_t bh[4], bl[4];
                LDSM_X4(bh, ba);
                LDSM_X4(bl, ba + 10240);
#pragma unroll
                for (int mi = 0; mi < 2; mi++) {
                    mma16816(acc[mi][2 * g],     ah[mi], bh[0], bh[1]);
                    mma16816(acc[mi][2 * g + 1], ah[mi], bh[2], bh[3]);
                    mma16816(acc[mi][2 * g],     al[mi], bh[0], bh[1]);
                    mma16816(acc[mi][2 * g + 1], al[mi], bh[2], bh[3]);
                    mma16816(acc[mi][2 * g],     ah[mi], bl[0], bl[1]);
                    mma16816(acc[mi][2 * g + 1], ah[mi], bl[2], bl[3]);
                }
            }
        }

        if (c < NCHK - 1) store_A_smem(smem_g + nbuf * BUF_B, tid, aR);
        CP_WAIT0();
        __syncthreads();
    }

    // Epilogue: add pos_emb; store fp32 Wh and bf16 hi/lo Wh.
    const int g = lane >> 2, t = lane & 3;
#pragma unroll
    for (int mi = 0; mi < 2; mi++) {
#pragma unroll
        for (int h2 = 0; h2 < 2; h2++) {
            const int row = m0 + wm * 32 + mi * 16 + g + h2 * 8;
            const int pos = positions[row];
            const float* pt = &pos_table[(size_t)pos * DOUT_];
            float* orow = &g_Wh[(size_t)row * DOUT_];
#pragma unroll
            for (int ni = 0; ni < 8; ni++) {
                const int col = n0 + wn * 64 + ni * 8 + t * 2;
                const float2 p = *(const float2*)&pt[col];
                float2 o;
                o.x = acc[mi][ni][h2 * 2 + 0] + p.x;
                o.y = acc[mi][ni][h2 * 2 + 1] + p.y;
                *(float2*)&orow[col] = o;
                __nv_bfloat16 hx = __float2bfloat16(o.x);
                __nv_bfloat16 hy = __float2bfloat16(o.y);
                __nv_bfloat16 lx = __float2bfloat16(o.x - __bfloat162float(hx));
                __nv_bfloat16 ly = __float2bfloat16(o.y - __bfloat162float(hy));
                *(uint32_t*)&g_Whbf_hi[(size_t)row * DOUT_ + col] = pack_bf2(hx, hy);
                *(uint32_t*)&g_Whbf_lo[(size_t)row * DOUT_ + col] = pack_bf2(lx, ly);
            }
        }
    }
}

// ---------------------------------------------------------------------------
// Kernel 2: s1 = Wh . a1, s2 = Wh . a2 per row. One warp per row.
// ---------------------------------------------------------------------------
__global__ void s12_kernel(const float* __restrict__ a1,
                           const float* __restrict__ a2) {
    __shared__ float sa1[DOUT_], sa2[DOUT_];
    const int tid = threadIdx.x;
    sa1[tid] = a1[tid];
    sa2[tid] = a2[tid];
    __syncthreads();

    const int warp = tid >> 5, lane = tid & 31;
    const int row = blockIdx.x * 8 + warp;
    const float* wr = &g_Wh[(size_t)row * DOUT_];

    float p1 = 0.f, p2 = 0.f;
#pragma unroll
    for (int c = 0; c < 2; c++) {
        int idx = (c * 32 + lane) * 4;
        float4 v = *(const float4*)&wr[idx];
        p1 += v.x * sa1[idx] + v.y * sa1[idx + 1] + v.z * sa1[idx + 2] + v.w * sa1[idx + 3];
        p2 += v.x * sa2[idx] + v.y * sa2[idx + 1] + v.z * sa2[idx + 2] + v.w * sa2[idx + 3];
    }
#pragma unroll
    for (int o = 16; o; o >>= 1) {
        p1 += __shfl_xor_sync(0xFFFFFFFFu, p1, o);
        p2 += __shfl_xor_sync(0xFFFFFFFFu, p2, o);
    }
    if (lane == 0) {
        g_s1[row] = p1;
        g_s2[row] = p2;
    }
}

// ---------------------------------------------------------------------------
// Kernel 3: masked softmax attention + h_prime = att @ Wh via mma.sync.
// One block per (batch b, 32 i-rows). 256 threads = 8 warps.
// Phase A: register softmax -> gmem att + smem bf16 hi/lo A-operand.
// Phase B: 3-term bf16 MMA, M=32 (2 warps) x N=256 (4 warps), K=512 in
//          16-row chunks of Whbf staged by double-buffered cp.async.
//
// smem byte layout (dynamic, 102400 B total):
//   A_hi: [32 rows][1040 B]   @ 0        (512 bf16 + 8 pad)
//   A_lo: same                @ 33280
//   B bufs: 2 x { hi [16][528] @ +0 ; lo @ +8448 }  @ 66560 (16896/buf)
//   s_s2: 512 floats          @ 100352
// ---------------------------------------------------------------------------
#define APAD    1040
#define A_LO_O  33280
#define B_BASE  66560
#define BSTRIDE 528
#define BCHUNK  16
#define NCHK3   (NN / BCHUNK)    // 32
#define BBUF3   16896
#define S2_OFF  100352
#define SMEM3_T 102400

extern __shared__ char sm3[];

__device__ __forceinline__ void stage_whbf(uint32_t sb, int buf, int c, int b,
                                           int tid) {
    const uint32_t dbase = sb + B_BASE + buf * BBUF3;
#pragma unroll
    for (int i = 0; i < 2; i++) {
        const int e = tid + i * 256;          // 0..511
        const int r = e >> 5;                 // 0..15
        const int seg = e & 31;               // 0..31 (16B segs of 512B row)
        const size_t gi = ((size_t)(b * NN + c * BCHUNK + r)) * DOUT_ + seg * 8;
        const uint32_t d = dbase + (uint32_t)(r * BSTRIDE + seg * 16);
        CP_ASYNC16(d,         (const void*)&g_Whbf_hi[gi]);
        CP_ASYNC16(d + 8448,  (const void*)&g_Whbf_lo[gi]);
    }
}

__global__ __launch_bounds__(256, 2)
void attn_kernel(const int* __restrict__ adj,
                 float* __restrict__ out_h,
                 float* __restrict__ out_att) {
    const uint32_t sb = smem_u32(sm3);
    float* s_s2 = (float*)(sm3 + S2_OFF);

    const int tid = threadIdx.x;
    const int wid = tid >> 5, lane = tid & 31;
    const int blk = blockIdx.x;
    const int b  = blk >> 4;           // 16 tiles per batch
    const int it = blk & 15;

    // Prefetch first Wh chunk while softmax runs.
    stage_whbf(sb, 0, 0, b, tid);
    CP_COMMIT();

    s_s2[tid]       = g_s2[b * NN + tid];
    s_s2[tid + 256] = g_s2[b * NN + tid + 256];
    __syncthreads();

    // ---- Phase A: per-row masked leaky-relu softmax (each warp: 4 rows) ----
    for (int r = 0; r < 4; r++) {
        const int li = wid * 4 + r;            // 0..31
        const int grow = b * NN + it * 32 + li;
        const float s1i = g_s1[grow];
        const int4* arow4 = (const int4*)&adj[(size_t)grow * NN];
        float4* gatt4 = (float4*)&out_att[(size_t)grow * NN];

        float4 v[4];
        float m = -CUDART_INF_F;
#pragma unroll
        for (int c = 0; c < 4; c++) {
            const int j = c * 32 + lane;       // float4 index
            const int4  av  = arow4[j];
            const float4 s2v = *(const float4*)&s_s2[j * 4];
            float4 e;
            e.x = s1i + s2v.x; e.x = e.x > 0.f ? e.x : SLOPE * e.x;
            e.y = s1i + s2v.y; e.y = e.y > 0.f ? e.y : SLOPE * e.y;
            e.z = s1i + s2v.z; e.z = e.z > 0.f ? e.z : SLOPE * e.z;
            e.w = s1i + s2v.w; e.w = e.w > 0.f ? e.w : SLOPE * e.w;
            e.x = (av.x > 0) ? e.x : NEGV;
            e.y = (av.y > 0) ? e.y : NEGV;
            e.z = (av.z > 0) ? e.z : NEGV;
            e.w = (av.w > 0) ? e.w : NEGV;
            v[c] = e;
            m = fmaxf(m, fmaxf(fmaxf(e.x, e.y), fmaxf(e.z, e.w)));
        }
#pragma unroll
        for (int o = 16; o; o >>= 1) m = fmaxf(m, __shfl_xor_sync(0xFFFFFFFFu, m, o));

        float s = 0.f;
#pragma unroll
        for (int c = 0; c < 4; c++) {
            v[c].x = __expf(v[c].x - m);
            v[c].y = __expf(v[c].y - m);
            v[c].z = __expf(v[c].z - m);
            v[c].w = __expf(v[c].w - m);
            s += (v[c].x + v[c].y) + (v[c].z + v[c].w);
        }
#pragma unroll
        for (int o = 16; o; o >>= 1) s += __shfl_xor_sync(0xFFFFFFFFu, s, o);
        const float rinv = 1.f / s;

#pragma unroll
        for (int c = 0; c < 4; c++) {
            const int j = c * 32 + lane;
            float4 p;
            p.x = v[c].x * rinv;
            p.y = v[c].y * rinv;
            p.z = v[c].z * rinv;
            p.w = v[c].w * rinv;
            gatt4[j] = p;
            __nv_bfloat16 hx = __float2bfloat16(p.x);
            __nv_bfloat16 hy = __float2bfloat16(p.y);
            __nv_bfloat16 hz = __float2bfloat16(p.z);
            __nv_bfloat16 hw = __float2bfloat16(p.w);
            __nv_bfloat16 lx = __float2bfloat16(p.x - __bfloat162float(hx));
            __nv_bfloat16 ly = __float2bfloat16(p.y - __bfloat162float(hy));
            __nv_bfloat16 lz = __float2bfloat16(p.z - __bfloat162float(hz));
            __nv_bfloat16 lw = __float2bfloat16(p.w - __bfloat162float(hw));
            uint2 hv; hv.x = pack_bf2(hx, hy); hv.y = pack_bf2(hz, hw);
            uint2 lv; lv.x = pack_bf2(lx, ly); lv.y = pack_bf2(lz, lw);
            char* arow = sm3 + li * APAD + j * 8;
            *(uint2*)(arow)           = hv;
            *(uint2*)(arow + A_LO_O)  = lv;
        }
    }

    // ---- Phase B: h_prime = att @ Wh_b, 3-term bf16 mma.sync ----
    const int wm = wid & 1;            // m16 half (rows 0-15 / 16-31)
    const int wn = wid >> 1;           // 0..3 -> n offset 64*wn

    const int a_r = wm * 16 + (lane & 15);
    const uint32_t a_base = sb + (uint32_t)(a_r * APAD + (lane >> 4) * 16);
    const uint32_t b_off  = (uint32_t)((lane & 15) * BSTRIDE +
                                       (wn * 64 + (lane >> 4) * 8) * 2);

    float acc[8][4];
#pragma unroll
    for (int ni = 0; ni < 8; ni++)
#pragma unroll
        for (int q = 0; q < 4; q++) acc[ni][q] = 0.f;

    for (int c = 0; c < NCHK3; c++) {
        const int buf = c & 1;
        if (c < NCHK3 - 1) {
            stage_whbf(sb, buf ^ 1, c + 1, b, tid);
            CP_COMMIT();
            CP_WAIT1();
        } else {
            CP_WAIT0();
        }
        __syncthreads();

        uint32_t ah[4], al[4];
        const uint32_t aa = a_base + (uint32_t)(c * 32);   // c*16 elems * 2B
        LDSM_X4(ah, aa);
        LDSM_X4(al, aa + A_LO_O);

        const uint32_t bbase = sb + B_BASE + buf * BBUF3 + b_off;
#pragma unroll
        for (int g = 0; g < 4; g++) {
            uint32_t bh[4], bl[4];
            LDSM_X4_T(bh, bbase + g * 32);                 // g*16 cols * 2B
            LDSM_X4_T(bl, bbase + g * 32 + 8448);
            mma16816(acc[2 * g],     ah, bh[0], bh[1]);
            mma16816(acc[2 * g + 1], ah, bh[2], bh[3]);
            mma16816(acc[2 * g],     al, bh[0], bh[1]);
            mma16816(acc[2 * g + 1], al, bh[2], bh[3]);
            mma16816(acc[2 * g],     ah, bl[0], bl[1]);
            mma16816(acc[2 * g + 1], ah, bl[2], bl[3]);
        }
        __syncthreads();
    }

    // Epilogue: write h_prime [32 x 256] tile.
    const int g = lane >> 2, t = lane & 3;
    const int rbase = b * NN + it * 32 + wm * 16;
#pragma unroll
    for (int h2 = 0; h2 < 2; h2++) {
        float* orow = &out_h[(size_t)(rbase + g + h2 * 8) * DOUT_];
#pragma unroll
        for (int ni = 0; ni < 8; ni++) {
            const int col = wn * 64 + ni * 8 + t * 2;
            float2 o;
            o.x = acc[ni][h2 * 2 + 0];
            o.y = acc[ni][h2 * 2 + 1];
            *(float2*)&orow[col] = o;
        }
    }
}

// ---------------------------------------------------------------------------
extern "C" void kernel_launch(void* const* d_in, const int* in_sizes, int n_in,
                              void* d_out, int out_size) {
    const float* h         = (const float*)d_in[0];
    const int*   adj       = (const int*)  d_in[1];
    const int*   positions = (const int*)  d_in[2];
    const float* W         = (const float*)d_in[3];
    const float* a1        = (const float*)d_in[4];
    const float* a2        = (const float*)d_in[5];
    const float* pos_table = (const float*)d_in[6];

    float* out_h   = (float*)d_out;                           // [32,512,256]
    float* out_att = (float*)d_out + (size_t)BB * NN * DOUT_; // [32,512,512]

    wt_convert_kernel<<<192, 256>>>(W);

    cudaFuncSetAttribute(gemm_wh_mma_kernel,
                         cudaFuncAttributeMaxDynamicSharedMemorySize, GSMEM);
    dim3 g1(DOUT_ / 128, MROWS / 128);   // (2, 128) = 256 CTAs
    gemm_wh_mma_kernel<<<g1, 256, GSMEM>>>(h, positions, pos_table);

    s12_kernel<<<MROWS / 8, 256>>>(a1, a2);

    cudaFuncSetAttribute(attn_kernel,
                         cudaFuncAttributeMaxDynamicSharedMemorySize, SMEM3_T);
    attn_kernel<<<BB * 16, 256, SMEM3_T>>>(adj, out_h, out_att);
}

// round 12
// speedup vs baseline: 5.7919x; 1.7690x over previous
#include <cuda_runtime.h>
#include <cuda_fp16.h>
#include <math_constants.h>
#include <cstdint>

#define BB    32
#define NN    512
#define DIN_  768
#define DOUT_ 256
#define MROWS (BB * NN)          // 16384
#define NEGV  (-9.0e15f)
#define SLOPE 0.2f

// Scratch (device globals: allocation-free)
__device__ float g_s1[MROWS];
__device__ float g_s2[MROWS];
__device__ __half g_WTf[DOUT_ * DIN_];   // W^T fp16, [256][768] K-major
__device__ __half g_Whf[MROWS * DOUT_];  // Wh fp16,  [row][d]     8 MB

// ---------------------------------------------------------------------------
// Helpers (plain sm_103 features: mma.sync, ldmatrix, cp.async)
// ---------------------------------------------------------------------------
__device__ __forceinline__ uint32_t smem_u32(const void* p) {
    uint32_t a;
    asm("{ .reg .u64 t; cvta.to.shared.u64 t, %1; cvt.u32.u64 %0, t; }"
        : "=r"(a) : "l"(p));
    return a;
}

#define LDSM_X4(r, addr)                                                      \
    asm volatile("ldmatrix.sync.aligned.m8n8.x4.shared.b16 {%0,%1,%2,%3}, [%4];" \
                 : "=r"((r)[0]), "=r"((r)[1]), "=r"((r)[2]), "=r"((r)[3])     \
                 : "r"(addr))
#define LDSM_X4_T(r, addr)                                                    \
    asm volatile("ldmatrix.sync.aligned.m8n8.x4.trans.shared.b16 {%0,%1,%2,%3}, [%4];" \
                 : "=r"((r)[0]), "=r"((r)[1]), "=r"((r)[2]), "=r"((r)[3])     \
                 : "r"(addr))

__device__ __forceinline__ void mma16816(float* c, const uint32_t* a,
                                         uint32_t b0, uint32_t b1) {
    asm volatile(
        "mma.sync.aligned.m16n8k16.row.col.f32.f16.f16.f32 "
        "{%0,%1,%2,%3}, {%4,%5,%6,%7}, {%8,%9}, {%0,%1,%2,%3};"
        : "+f"(c[0]), "+f"(c[1]), "+f"(c[2]), "+f"(c[3])
        : "r"(a[0]), "r"(a[1]), "r"(a[2]), "r"(a[3]), "r"(b0), "r"(b1));
}

#define CP_ASYNC16(dst, src) \
    asm volatile("cp.async.cg.shared.global [%0], [%1], 16;" :: "r"(dst), "l"(src))
#define CP_COMMIT()  asm volatile("cp.async.commit_group;" ::: "memory")
#define CP_WAIT0()   asm volatile("cp.async.wait_group 0;" ::: "memory")
#define CP_WAIT2()   asm volatile("cp.async.wait_group 2;" ::: "memory")

__device__ __forceinline__ uint32_t pack_h2(__half a, __half b) {
    __half2 t(a, b);
    return *(uint32_t*)&t;
}

// ---------------------------------------------------------------------------
// Kernel 0: W [768,256] fp32  ->  W^T fp16 [256][768]
// ---------------------------------------------------------------------------
__global__ void wt_convert_kernel(const float* __restrict__ W) {
    const int idx = blockIdx.x * 256 + threadIdx.x;   // 0..49151
    const int k  = idx >> 6;                          // 0..767
    const int n4 = (idx & 63) * 4;                    // 0..252
    const float4 v = *(const float4*)&W[(size_t)k * DOUT_ + n4];
    g_WTf[(size_t)(n4 + 0) * DIN_ + k] = __float2half(v.x);
    g_WTf[(size_t)(n4 + 1) * DIN_ + k] = __float2half(v.y);
    g_WTf[(size_t)(n4 + 2) * DIN_ + k] = __float2half(v.z);
    g_WTf[(size_t)(n4 + 3) * DIN_ + k] = __float2half(v.w);
}

// ---------------------------------------------------------------------------
// Kernel 1: Wh = h @ W + pos_table[positions], fp16 single-term mma.sync.
// Block tile 128x128, 8 warps (4m x 2n), warp tile 32x64, K-chunk 32,
// double-buffered smem, cp.async for B. Output: g_Whf (fp16).
// smem per buffer: A [128][40] fp16 @0 (10240 B), B [128][40] fp16 @10240.
// ---------------------------------------------------------------------------
#define PAD    40
#define CHUNK  32
#define NCHK   (DIN_ / CHUNK)     // 24
#define BUF_B  20480
#define GSMEM  (2 * BUF_B)        // 40960

extern __shared__ char smem_g[];

__device__ __forceinline__ void load_A_regs(const float* __restrict__ h,
                                            int m0, int kbase, int tid,
                                            float4* aR) {
#pragma unroll
    for (int i = 0; i < 4; i++) {
        const int e = tid + i * 256;          // 0..1023
        const int row = e >> 3;               // 0..127
        const int c4  = (e & 7) * 4;          // 0..28
        aR[i] = *(const float4*)&h[(size_t)(m0 + row) * DIN_ + kbase + c4];
    }
}

__device__ __forceinline__ void store_A_smem(char* s, int tid, const float4* aR) {
#pragma unroll
    for (int i = 0; i < 4; i++) {
        const int e = tid + i * 256;
        const int row = e >> 3;
        const int c4  = (e & 7) * 4;
        const float4 v = aR[i];
        uint2 hv;
        hv.x = pack_h2(__float2half(v.x), __float2half(v.y));
        hv.y = pack_h2(__float2half(v.z), __float2half(v.w));
        *(uint2*)(s + (uint32_t)(row * (PAD * 2) + c4 * 2)) = hv;
    }
}

__device__ __forceinline__ void cpasync_B(uint32_t b_byte, int n0, int kbase,
                                          int tid) {
#pragma unroll
    for (int i = 0; i < 2; i++) {
        const int e = tid + i * 256;          // 0..511
        const int row = e >> 2;               // 0..127
        const int q   = e & 3;                // 0..3
        const size_t gi = (size_t)(n0 + row) * DIN_ + kbase + q * 8;
        CP_ASYNC16(b_byte + (uint32_t)(row * (PAD * 2) + q * 16),
                   (const void*)&g_WTf[gi]);
    }
}

__global__ __launch_bounds__(256, 2)
void gemm_wh_mma_kernel(const float* __restrict__ h,
                        const int*   __restrict__ positions,
                        const float* __restrict__ pos_table) {
    const uint32_t sb = smem_u32(smem_g);
    const int tid  = threadIdx.x;
    const int wid  = tid >> 5;
    const int lane = tid & 31;
    const int wm = wid >> 1;           // 0..3
    const int wn = wid & 1;            // 0..1
    const int m0 = blockIdx.y * 128;
    const int n0 = blockIdx.x * 128;

    const int lr = lane & 15;
    const int lk = (lane >> 4) * 8;
    const int bn = ((lane >> 4) * 8) + (lane & 7);
    const int bk = ((lane >> 3) & 1) * 8;

    float acc[2][8][4];
#pragma unroll
    for (int mi = 0; mi < 2; mi++)
#pragma unroll
        for (int ni = 0; ni < 8; ni++)
#pragma unroll
            for (int q = 0; q < 4; q++) acc[mi][ni][q] = 0.f;

    float4 aR[4];

    cpasync_B(sb + 10240, n0, 0, tid);
    CP_COMMIT();
    load_A_regs(h, m0, 0, tid, aR);
    store_A_smem(smem_g, tid, aR);
    CP_WAIT0();
    __syncthreads();

    for (int c = 0; c < NCHK; c++) {
        const int buf  = c & 1;
        const int nbuf = buf ^ 1;

        if (c < NCHK - 1) {
            const int kn = (c + 1) * CHUNK;
            cpasync_B(sb + nbuf * BUF_B + 10240, n0, kn, tid);
            CP_COMMIT();
            load_A_regs(h, m0, kn, tid, aR);
        }

        const uint32_t AS = sb + buf * BUF_B;
        const uint32_t BS = AS + 10240;

#pragma unroll
        for (int k16 = 0; k16 < CHUNK; k16 += 16) {
            uint32_t ah[2][4];
#pragma unroll
            for (int mi = 0; mi < 2; mi++) {
                const uint32_t aa =
                    AS + (uint32_t)(((wm * 32 + mi * 16 + lr) * PAD + k16 + lk) * 2);
                LDSM_X4(ah[mi], aa);
            }
#pragma unroll
            for (int g = 0; g < 4; g++) {
                const uint32_t ba =
                    BS + (uint32_t)(((wn * 64 + g * 16 + bn) * PAD + k16 + bk) * 2);
                uint32_t bh[4];
                LDSM_X4(bh, ba);
#pragma unroll
                for (int mi = 0; mi < 2; mi++) {
                    mma16816(acc[mi][2 * g],     ah[mi], bh[0], bh[1]);
                    mma16816(acc[mi][2 * g + 1], ah[mi], bh[2], bh[3]);
                }
            }
        }

        if (c < NCHK - 1) store_A_smem(smem_g + nbuf * BUF_B, tid, aR);
        CP_WAIT0();
        __syncthreads();
    }

    // Epilogue: add pos_emb; store Wh as fp16.
    const int g = lane >> 2, t = lane & 3;
#pragma unroll
    for (int mi = 0; mi < 2; mi++) {
#pragma unroll
        for (int h2 = 0; h2 < 2; h2++) {
            const int row = m0 + wm * 32 + mi * 16 + g + h2 * 8;
            const int pos = positions[row];
            const float* pt = &pos_table[(size_t)pos * DOUT_];
#pragma unroll
            for (int ni = 0; ni < 8; ni++) {
                const int col = n0 + wn * 64 + ni * 8 + t * 2;
                const float2 p = *(const float2*)&pt[col];
                const float ox = acc[mi][ni][h2 * 2 + 0] + p.x;
                const float oy = acc[mi][ni][h2 * 2 + 1] + p.y;
                *(uint32_t*)&g_Whf[(size_t)row * DOUT_ + col] =
                    pack_h2(__float2half(ox), __float2half(oy));
            }
        }
    }
}

// ---------------------------------------------------------------------------
// Kernel 2: s1 = Wh . a1, s2 = Wh . a2 per row (fp16 Wh). One warp per row.
// ---------------------------------------------------------------------------
__global__ void s12_kernel(const float* __restrict__ a1,
                           const float* __restrict__ a2) {
    __shared__ float sa1[DOUT_], sa2[DOUT_];
    const int tid = threadIdx.x;
    sa1[tid] = a1[tid];
    sa2[tid] = a2[tid];
    __syncthreads();

    const int warp = tid >> 5, lane = tid & 31;
    const int row = blockIdx.x * 8 + warp;

    // 8 halves (16 B) per lane covers the 256-dim row.
    const uint4 u = *(const uint4*)&g_Whf[(size_t)row * DOUT_ + lane * 8];
    const __half2* hp = (const __half2*)&u;
    const int base = lane * 8;
    float p1 = 0.f, p2 = 0.f;
#pragma unroll
    for (int q = 0; q < 4; q++) {
        const float2 f = __half22float2(hp[q]);
        p1 += f.x * sa1[base + 2 * q] + f.y * sa1[base + 2 * q + 1];
        p2 += f.x * sa2[base + 2 * q] + f.y * sa2[base + 2 * q + 1];
    }
#pragma unroll
    for (int o = 16; o; o >>= 1) {
        p1 += __shfl_xor_sync(0xFFFFFFFFu, p1, o);
        p2 += __shfl_xor_sync(0xFFFFFFFFu, p2, o);
    }
    if (lane == 0) {
        g_s1[row] = p1;
        g_s2[row] = p2;
    }
}

// ---------------------------------------------------------------------------
// Kernel 3: masked softmax attention + h_prime = att @ Wh (fp16 mma.sync).
// One block per (batch b, 32 i-rows). 256 threads = 8 warps.
// Phase A: register softmax -> gmem att (fp32) + smem fp16 A-operand.
// Phase B: single-term fp16 MMA, M=32 (2 warps) x N=256 (4 warps), K=512 in
//          16-row chunks, 4-stage cp.async pipeline, ONE syncthreads/chunk.
//
// smem (dynamic, 69120 B):
//   A:  [32][1040 B]            @ 0      (512 fp16 + 16B pad)
//   B:  4 stages x [16][528 B]  @ 33280  (8448 B/stage)
//   s2: 512 floats              @ 67072
// ---------------------------------------------------------------------------
#define APAD    1040
#define B_BASE  33280
#define BSTRIDE 528
#define BSTAGE  8448
#define BCHUNK  16
#define NCHK3   (NN / BCHUNK)    // 32
#define S2_OFF  67072
#define SMEM3_T 69120

extern __shared__ char sm3[];

__device__ __forceinline__ void stage_whf(uint32_t sb, int buf, int c, int b,
                                          int tid) {
    const uint32_t dbase = sb + B_BASE + buf * BSTAGE;
#pragma unroll
    for (int i = 0; i < 2; i++) {
        const int e = tid + i * 256;          // 0..511
        const int r = e >> 5;                 // 0..15
        const int seg = e & 31;               // 0..31 (16B segs of 512B row)
        const size_t gi = ((size_t)(b * NN + c * BCHUNK + r)) * DOUT_ + seg * 8;
        CP_ASYNC16(dbase + (uint32_t)(r * BSTRIDE + seg * 16),
                   (const void*)&g_Whf[gi]);
    }
}

__global__ __launch_bounds__(256, 3)
void attn_kernel(const int* __restrict__ adj,
                 float* __restrict__ out_h,
                 float* __restrict__ out_att) {
    const uint32_t sb = smem_u32(sm3);
    float* s_s2 = (float*)(sm3 + S2_OFF);

    const int tid = threadIdx.x;
    const int wid = tid >> 5, lane = tid & 31;
    const int blk = blockIdx.x;
    const int b  = blk >> 4;           // 16 tiles per batch
    const int it = blk & 15;

    // Prologue: stage first 3 Wh chunks; they land while softmax runs.
    stage_whf(sb, 0, 0, b, tid); CP_COMMIT();
    stage_whf(sb, 1, 1, b, tid); CP_COMMIT();
    stage_whf(sb, 2, 2, b, tid); CP_COMMIT();

    s_s2[tid]       = g_s2[b * NN + tid];
    s_s2[tid + 256] = g_s2[b * NN + tid + 256];
    __syncthreads();

    // ---- Phase A: per-row masked leaky-relu softmax (each warp: 4 rows) ----
    for (int r = 0; r < 4; r++) {
        const int li = wid * 4 + r;            // 0..31
        const int grow = b * NN + it * 32 + li;
        const float s1i = g_s1[grow];
        const int4* arow4 = (const int4*)&adj[(size_t)grow * NN];
        float4* gatt4 = (float4*)&out_att[(size_t)grow * NN];

        float4 v[4];
        float m = -CUDART_INF_F;
#pragma unroll
        for (int c = 0; c < 4; c++) {
            const int j = c * 32 + lane;       // float4 index
            const int4  av  = arow4[j];
            const float4 s2v = *(const float4*)&s_s2[j * 4];
            float4 e;
            e.x = s1i + s2v.x; e.x = e.x > 0.f ? e.x : SLOPE * e.x;
            e.y = s1i + s2v.y; e.y = e.y > 0.f ? e.y : SLOPE * e.y;
            e.z = s1i + s2v.z; e.z = e.z > 0.f ? e.z : SLOPE * e.z;
            e.w = s1i + s2v.w; e.w = e.w > 0.f ? e.w : SLOPE * e.w;
            e.x = (av.x > 0) ? e.x : NEGV;
            e.y = (av.y > 0) ? e.y : NEGV;
            e.z = (av.z > 0) ? e.z : NEGV;
            e.w = (av.w > 0) ? e.w : NEGV;
            v[c] = e;
            m = fmaxf(m, fmaxf(fmaxf(e.x, e.y), fmaxf(e.z, e.w)));
        }
#pragma unroll
        for (int o = 16; o; o >>= 1) m = fmaxf(m, __shfl_xor_sync(0xFFFFFFFFu, m, o));

        float s = 0.f;
#pragma unroll
        for (int c = 0; c < 4; c++) {
            v[c].x = __expf(v[c].x - m);
            v[c].y = __expf(v[c].y - m);
            v[c].z = __expf(v[c].z - m);
            v[c].w = __expf(v[c].w - m);
            s += (v[c].x + v[c].y) + (v[c].z + v[c].w);
        }
#pragma unroll
        for (int o = 16; o; o >>= 1) s += __shfl_xor_sync(0xFFFFFFFFu, s, o);
        const float rinv = 1.f / s;

#pragma unroll
        for (int c = 0; c < 4; c++) {
            const int j = c * 32 + lane;
            float4 p;
            p.x = v[c].x * rinv;
            p.y = v[c].y * rinv;
            p.z = v[c].z * rinv;
            p.w = v[c].w * rinv;
            gatt4[j] = p;
            uint2 hv;
            hv.x = pack_h2(__float2half(p.x), __float2half(p.y));
            hv.y = pack_h2(__float2half(p.z), __float2half(p.w));
            *(uint2*)(sm3 + li * APAD + j * 8) = hv;
        }
    }

    // ---- Phase B: h_prime = att @ Wh_b, single-term fp16 mma.sync ----
    const int wm = wid & 1;            // m16 half (rows 0-15 / 16-31)
    const int wn = wid >> 1;           // 0..3 -> n offset 64*wn

    const int a_r = wm * 16 + (lane & 15);
    const uint32_t a_base = sb + (uint32_t)(a_r * APAD + (lane >> 4) * 16);
    const uint32_t b_off  = (uint32_t)((lane & 15) * BSTRIDE +
                                       (wn * 64 + (lane >> 4) * 8) * 2);

    float acc[8][4];
#pragma unroll
    for (int ni = 0; ni < 8; ni++)
#pragma unroll
        for (int q = 0; q < 4; q++) acc[ni][q] = 0.f;

    for (int c = 0; c < NCHK3; c++) {
        const int buf = c & 3;
        // Own-thread copies of chunk c complete:
        if (c < NCHK3 - 2) { CP_WAIT2(); } else { CP_WAIT0(); }
        // All threads' chunk-c copies visible + all done reading chunk c-1:
        __syncthreads();
        // Stage chunk c+3 into the buffer chunk c-1 vacated.
        if (c + 3 < NCHK3) { stage_whf(sb, (c + 3) & 3, c + 3, b, tid); CP_COMMIT(); }

        uint32_t ah[4];
        LDSM_X4(ah, a_base + (uint32_t)(c * 32));          // c*16 elems * 2B

        const uint32_t bbase = sb + B_BASE + buf * BSTAGE + b_off;
#pragma unroll
        for (int g = 0; g < 4; g++) {
            uint32_t bh[4];
            LDSM_X4_T(bh, bbase + g * 32);                 // g*16 cols * 2B
            mma16816(acc[2 * g],     ah, bh[0], bh[1]);
            mma16816(acc[2 * g + 1], ah, bh[2], bh[3]);
        }
    }

    // Epilogue: write h_prime [32 x 256] tile.
    const int g = lane >> 2, t = lane & 3;
    const int rbase = b * NN + it * 32 + wm * 16;
#pragma unroll
    for (int h2 = 0; h2 < 2; h2++) {
        float* orow = &out_h[(size_t)(rbase + g + h2 * 8) * DOUT_];
#pragma unroll
        for (int ni = 0; ni < 8; ni++) {
            const int col = wn * 64 + ni * 8 + t * 2;
            float2 o;
            o.x = acc[ni][h2 * 2 + 0];
            o.y = acc[ni][h2 * 2 + 1];
            *(float2*)&orow[col] = o;
        }
    }
}

// ---------------------------------------------------------------------------
extern "C" void kernel_launch(void* const* d_in, const int* in_sizes, int n_in,
                              void* d_out, int out_size) {
    const float* h         = (const float*)d_in[0];
    const int*   adj       = (const int*)  d_in[1];
    const int*   positions = (const int*)  d_in[2];
    const float* W         = (const float*)d_in[3];
    const float* a1        = (const float*)d_in[4];
    const float* a2        = (const float*)d_in[5];
    const float* pos_table = (const float*)d_in[6];

    float* out_h   = (float*)d_out;                           // [32,512,256]
    float* out_att = (float*)d_out + (size_t)BB * NN * DOUT_; // [32,512,512]

    wt_convert_kernel<<<192, 256>>>(W);

    cudaFuncSetAttribute(gemm_wh_mma_kernel,
                         cudaFuncAttributeMaxDynamicSharedMemorySize, GSMEM);
    dim3 g1(DOUT_ / 128, MROWS / 128);   // (2, 128) = 256 CTAs
    gemm_wh_mma_kernel<<<g1, 256, GSMEM>>>(h, positions, pos_table);

    s12_kernel<<<MROWS / 8, 256>>>(a1, a2);

    cudaFuncSetAttribute(attn_kernel,
                         cudaFuncAttributeMaxDynamicSharedMemorySize, SMEM3_T);
    attn_kernel<<<BB * 16, 256, SMEM3_T>>>(adj, out_h, out_att);
}

// round 13
// speedup vs baseline: 6.8029x; 1.1745x over previous
#include <cuda_runtime.h>
#include <cuda_fp16.h>
#include <math_constants.h>
#include <cstdint>

#define BB    32
#define NN    512
#define DIN_  768
#define DOUT_ 256
#define MROWS (BB * NN)          // 16384
#define NEGV  (-9.0e15f)
#define SLOPE 0.2f

// Scratch (device globals: allocation-free)
__device__ float g_s1[MROWS];
__device__ float g_s2[MROWS];
__device__ __half g_WTf[DOUT_ * DIN_];   // W^T fp16, [256][768] K-major
__device__ __half g_Whf[MROWS * DOUT_];  // Wh fp16,  [row][d]     8 MB

// ---------------------------------------------------------------------------
// Helpers
// ---------------------------------------------------------------------------
__device__ __forceinline__ uint32_t smem_u32(const void* p) {
    uint32_t a;
    asm("{ .reg .u64 t; cvta.to.shared.u64 t, %1; cvt.u32.u64 %0, t; }"
        : "=r"(a) : "l"(p));
    return a;
}

#define LDSM_X4(r, addr)                                                      \
    asm volatile("ldmatrix.sync.aligned.m8n8.x4.shared.b16 {%0,%1,%2,%3}, [%4];" \
                 : "=r"((r)[0]), "=r"((r)[1]), "=r"((r)[2]), "=r"((r)[3])     \
                 : "r"(addr))
#define LDSM_X4_T(r, addr)                                                    \
    asm volatile("ldmatrix.sync.aligned.m8n8.x4.trans.shared.b16 {%0,%1,%2,%3}, [%4];" \
                 : "=r"((r)[0]), "=r"((r)[1]), "=r"((r)[2]), "=r"((r)[3])     \
                 : "r"(addr))

__device__ __forceinline__ void mma16816(float* c, const uint32_t* a,
                                         uint32_t b0, uint32_t b1) {
    asm volatile(
        "mma.sync.aligned.m16n8k16.row.col.f32.f16.f16.f32 "
        "{%0,%1,%2,%3}, {%4,%5,%6,%7}, {%8,%9}, {%0,%1,%2,%3};"
        : "+f"(c[0]), "+f"(c[1]), "+f"(c[2]), "+f"(c[3])
        : "r"(a[0]), "r"(a[1]), "r"(a[2]), "r"(a[3]), "r"(b0), "r"(b1));
}

#define CP_ASYNC16(dst, src) \
    asm volatile("cp.async.cg.shared.global [%0], [%1], 16;" :: "r"(dst), "l"(src))
#define CP_COMMIT()  asm volatile("cp.async.commit_group;" ::: "memory")
#define CP_WAIT0()   asm volatile("cp.async.wait_group 0;" ::: "memory")
#define CP_WAIT2()   asm volatile("cp.async.wait_group 2;" ::: "memory")

__device__ __forceinline__ uint32_t pack_h2(__half a, __half b) {
    __half2 t(a, b);
    return *(uint32_t*)&t;
}

// ---------------------------------------------------------------------------
// Kernel 0: W -> W^T fp16; also zero s1/s2 accumulators for the fused dots.
// ---------------------------------------------------------------------------
__global__ void wt_convert_kernel(const float* __restrict__ W) {
    const int idx = blockIdx.x * 256 + threadIdx.x;   // 0..49151
    if (idx < MROWS) { g_s1[idx] = 0.f; g_s2[idx] = 0.f; }
    const int k  = idx >> 6;                          // 0..767
    const int n4 = (idx & 63) * 4;                    // 0..252
    const float4 v = *(const float4*)&W[(size_t)k * DOUT_ + n4];
    g_WTf[(size_t)(n4 + 0) * DIN_ + k] = __float2half(v.x);
    g_WTf[(size_t)(n4 + 1) * DIN_ + k] = __float2half(v.y);
    g_WTf[(size_t)(n4 + 2) * DIN_ + k] = __float2half(v.z);
    g_WTf[(size_t)(n4 + 3) * DIN_ + k] = __float2half(v.w);
}

// ---------------------------------------------------------------------------
// Kernel 1: Wh = h @ W + pos_table[positions] (fp16 mma.sync) + fused
// s1/s2 row-dots (shuffle-reduce + atomicAdd).
// Block tile 128x128, 8 warps (4m x 2n), K-chunk 32, double-buffered smem.
// ---------------------------------------------------------------------------
#define PAD    40
#define CHUNK  32
#define NCHK   (DIN_ / CHUNK)     // 24
#define BUF_B  20480
#define GSMEM  (2 * BUF_B)        // 40960

extern __shared__ char smem_g[];

__device__ __forceinline__ void load_A_regs(const float* __restrict__ h,
                                            int m0, int kbase, int tid,
                                            float4* aR) {
#pragma unroll
    for (int i = 0; i < 4; i++) {
        const int e = tid + i * 256;          // 0..1023
        const int row = e >> 3;               // 0..127
        const int c4  = (e & 7) * 4;          // 0..28
        aR[i] = *(const float4*)&h[(size_t)(m0 + row) * DIN_ + kbase + c4];
    }
}

__device__ __forceinline__ void store_A_smem(char* s, int tid, const float4* aR) {
#pragma unroll
    for (int i = 0; i < 4; i++) {
        const int e = tid + i * 256;
        const int row = e >> 3;
        const int c4  = (e & 7) * 4;
        const float4 v = aR[i];
        uint2 hv;
        hv.x = pack_h2(__float2half(v.x), __float2half(v.y));
        hv.y = pack_h2(__float2half(v.z), __float2half(v.w));
        *(uint2*)(s + (uint32_t)(row * (PAD * 2) + c4 * 2)) = hv;
    }
}

__device__ __forceinline__ void cpasync_B(uint32_t b_byte, int n0, int kbase,
                                          int tid) {
#pragma unroll
    for (int i = 0; i < 2; i++) {
        const int e = tid + i * 256;          // 0..511
        const int row = e >> 2;               // 0..127
        const int q   = e & 3;                // 0..3
        const size_t gi = (size_t)(n0 + row) * DIN_ + kbase + q * 8;
        CP_ASYNC16(b_byte + (uint32_t)(row * (PAD * 2) + q * 16),
                   (const void*)&g_WTf[gi]);
    }
}

__global__ __launch_bounds__(256, 2)
void gemm_wh_mma_kernel(const float* __restrict__ h,
                        const int*   __restrict__ positions,
                        const float* __restrict__ pos_table,
                        const float* __restrict__ a1,
                        const float* __restrict__ a2) {
    const uint32_t sb = smem_u32(smem_g);
    const int tid  = threadIdx.x;
    const int wid  = tid >> 5;
    const int lane = tid & 31;
    const int wm = wid >> 1;           // 0..3
    const int wn = wid & 1;            // 0..1
    const int m0 = blockIdx.y * 128;
    const int n0 = blockIdx.x * 128;

    const int lr = lane & 15;
    const int lk = (lane >> 4) * 8;
    const int bn = ((lane >> 4) * 8) + (lane & 7);
    const int bk = ((lane >> 3) & 1) * 8;

    float acc[2][8][4];
#pragma unroll
    for (int mi = 0; mi < 2; mi++)
#pragma unroll
        for (int ni = 0; ni < 8; ni++)
#pragma unroll
            for (int q = 0; q < 4; q++) acc[mi][ni][q] = 0.f;

    float4 aR[4];

    cpasync_B(sb + 10240, n0, 0, tid);
    CP_COMMIT();
    load_A_regs(h, m0, 0, tid, aR);
    store_A_smem(smem_g, tid, aR);
    CP_WAIT0();
    __syncthreads();

    for (int c = 0; c < NCHK; c++) {
        const int buf  = c & 1;
        const int nbuf = buf ^ 1;

        if (c < NCHK - 1) {
            const int kn = (c + 1) * CHUNK;
            cpasync_B(sb + nbuf * BUF_B + 10240, n0, kn, tid);
            CP_COMMIT();
            load_A_regs(h, m0, kn, tid, aR);
        }

        const uint32_t AS = sb + buf * BUF_B;
        const uint32_t BS = AS + 10240;

#pragma unroll
        for (int k16 = 0; k16 < CHUNK; k16 += 16) {
            uint32_t ah[2][4];
#pragma unroll
            for (int mi = 0; mi < 2; mi++) {
                const uint32_t aa =
                    AS + (uint32_t)(((wm * 32 + mi * 16 + lr) * PAD + k16 + lk) * 2);
                LDSM_X4(ah[mi], aa);
            }
#pragma unroll
            for (int g = 0; g < 4; g++) {
                const uint32_t ba =
                    BS + (uint32_t)(((wn * 64 + g * 16 + bn) * PAD + k16 + bk) * 2);
                uint32_t bh[4];
                LDSM_X4(bh, ba);
#pragma unroll
                for (int mi = 0; mi < 2; mi++) {
                    mma16816(acc[mi][2 * g],     ah[mi], bh[0], bh[1]);
                    mma16816(acc[mi][2 * g + 1], ah[mi], bh[2], bh[3]);
                }
            }
        }

        if (c < NCHK - 1) store_A_smem(smem_g + nbuf * BUF_B, tid, aR);
        CP_WAIT0();
        __syncthreads();
    }

    // Epilogue: add pos_emb; store fp16 Wh; fused partial s1/s2 dots.
    const int g = lane >> 2, t = lane & 3;
    float p1[2][2], p2[2][2];
#pragma unroll
    for (int mi = 0; mi < 2; mi++)
#pragma unroll
        for (int h2 = 0; h2 < 2; h2++) { p1[mi][h2] = 0.f; p2[mi][h2] = 0.f; }

#pragma unroll
    for (int mi = 0; mi < 2; mi++) {
#pragma unroll
        for (int h2 = 0; h2 < 2; h2++) {
            const int row = m0 + wm * 32 + mi * 16 + g + h2 * 8;
            const int pos = positions[row];
            const float* pt = &pos_table[(size_t)pos * DOUT_];
#pragma unroll
            for (int ni = 0; ni < 8; ni++) {
                const int col = n0 + wn * 64 + ni * 8 + t * 2;
                const float2 p = *(const float2*)&pt[col];
                const float ox = acc[mi][ni][h2 * 2 + 0] + p.x;
                const float oy = acc[mi][ni][h2 * 2 + 1] + p.y;
                *(uint32_t*)&g_Whf[(size_t)row * DOUT_ + col] =
                    pack_h2(__float2half(ox), __float2half(oy));
                const float2 va1 = *(const float2*)&a1[col];
                const float2 va2 = *(const float2*)&a2[col];
                p1[mi][h2] += ox * va1.x + oy * va1.y;
                p2[mi][h2] += ox * va2.x + oy * va2.y;
            }
        }
    }
    // Reduce over the 4 t-lanes (consecutive lanes share g => same rows).
#pragma unroll
    for (int mi = 0; mi < 2; mi++)
#pragma unroll
        for (int h2 = 0; h2 < 2; h2++) {
            float v1 = p1[mi][h2], v2 = p2[mi][h2];
            v1 += __shfl_xor_sync(0xFFFFFFFFu, v1, 1);
            v1 += __shfl_xor_sync(0xFFFFFFFFu, v1, 2);
            v2 += __shfl_xor_sync(0xFFFFFFFFu, v2, 1);
            v2 += __shfl_xor_sync(0xFFFFFFFFu, v2, 2);
            if (t == 0) {
                const int row = m0 + wm * 32 + mi * 16 + g + h2 * 8;
                atomicAdd(&g_s1[row], v1);
                atomicAdd(&g_s2[row], v2);
            }
        }
}

// ---------------------------------------------------------------------------
// Kernel 2: masked softmax attention + h_prime = att @ Wh (fp16 mma.sync).
// One block per (batch b, 64 i-rows): grid 256 = single wave at 2 CTA/SM.
// Phase A: register softmax -> gmem att (fp32) + smem fp16 A-operand (8 rows/warp).
// Phase B: M=64 (4m warps) x N=256 (2n warps, 128 each), K=512 in 16-row
//          chunks, 4-stage cp.async pipeline, ONE syncthreads/chunk.
//
// smem (dynamic, 102400 B):
//   A:  [64][1040 B]            @ 0      (512 fp16 + 16B pad)
//   B:  4 stages x [16][528 B]  @ 66560  (8448 B/stage)
//   s2: 512 floats              @ 100352
// ---------------------------------------------------------------------------
#define APAD    1040
#define B_BASE  66560
#define BSTRIDE 528
#define BSTAGE  8448
#define BCHUNK  16
#define NCHK3   (NN / BCHUNK)    // 32
#define S2_OFF  100352
#define SMEM3_T 102400

extern __shared__ char sm3[];

__device__ __forceinline__ void stage_whf(uint32_t sb, int buf, int c, int b,
                                          int tid) {
    const uint32_t dbase = sb + B_BASE + buf * BSTAGE;
#pragma unroll
    for (int i = 0; i < 2; i++) {
        const int e = tid + i * 256;          // 0..511
        const int r = e >> 5;                 // 0..15
        const int seg = e & 31;               // 0..31 (16B segs of 512B row)
        const size_t gi = ((size_t)(b * NN + c * BCHUNK + r)) * DOUT_ + seg * 8;
        CP_ASYNC16(dbase + (uint32_t)(r * BSTRIDE + seg * 16),
                   (const void*)&g_Whf[gi]);
    }
}

__global__ __launch_bounds__(256, 2)
void attn_kernel(const int* __restrict__ adj,
                 float* __restrict__ out_h,
                 float* __restrict__ out_att) {
    const uint32_t sb = smem_u32(sm3);
    float* s_s2 = (float*)(sm3 + S2_OFF);

    const int tid = threadIdx.x;
    const int wid = tid >> 5, lane = tid & 31;
    const int blk = blockIdx.x;
    const int b  = blk >> 3;           // 8 tiles of 64 rows per batch
    const int it = blk & 7;

    // Prologue: stage first 3 Wh chunks; they land while softmax runs.
    stage_whf(sb, 0, 0, b, tid); CP_COMMIT();
    stage_whf(sb, 1, 1, b, tid); CP_COMMIT();
    stage_whf(sb, 2, 2, b, tid); CP_COMMIT();

    s_s2[tid]       = g_s2[b * NN + tid];
    s_s2[tid + 256] = g_s2[b * NN + tid + 256];
    __syncthreads();

    // ---- Phase A: per-row masked leaky-relu softmax (each warp: 8 rows) ----
    for (int r = 0; r < 8; r++) {
        const int li = wid * 8 + r;            // 0..63
        const int grow = b * NN + it * 64 + li;
        const float s1i = g_s1[grow];
        const int4* arow4 = (const int4*)&adj[(size_t)grow * NN];
        float4* gatt4 = (float4*)&out_att[(size_t)grow * NN];

        float4 v[4];
        float m = -CUDART_INF_F;
#pragma unroll
        for (int c = 0; c < 4; c++) {
            const int j = c * 32 + lane;       // float4 index
            const int4  av  = arow4[j];
            const float4 s2v = *(const float4*)&s_s2[j * 4];
            float4 e;
            e.x = s1i + s2v.x; e.x = e.x > 0.f ? e.x : SLOPE * e.x;
            e.y = s1i + s2v.y; e.y = e.y > 0.f ? e.y : SLOPE * e.y;
            e.z = s1i + s2v.z; e.z = e.z > 0.f ? e.z : SLOPE * e.z;
            e.w = s1i + s2v.w; e.w = e.w > 0.f ? e.w : SLOPE * e.w;
            e.x = (av.x > 0) ? e.x : NEGV;
            e.y = (av.y > 0) ? e.y : NEGV;
            e.z = (av.z > 0) ? e.z : NEGV;
            e.w = (av.w > 0) ? e.w : NEGV;
            v[c] = e;
            m = fmaxf(m, fmaxf(fmaxf(e.x, e.y), fmaxf(e.z, e.w)));
        }
#pragma unroll
        for (int o = 16; o; o >>= 1) m = fmaxf(m, __shfl_xor_sync(0xFFFFFFFFu, m, o));

        float s = 0.f;
#pragma unroll
        for (int c = 0; c < 4; c++) {
            v[c].x = __expf(v[c].x - m);
            v[c].y = __expf(v[c].y - m);
            v[c].z = __expf(v[c].z - m);
            v[c].w = __expf(v[c].w - m);
            s += (v[c].x + v[c].y) + (v[c].z + v[c].w);
        }
#pragma unroll
        for (int o = 16; o; o >>= 1) s += __shfl_xor_sync(0xFFFFFFFFu, s, o);
        const float rinv = 1.f / s;

#pragma unroll
        for (int c = 0; c < 4; c++) {
            const int j = c * 32 + lane;
            float4 p;
            p.x = v[c].x * rinv;
            p.y = v[c].y * rinv;
            p.z = v[c].z * rinv;
            p.w = v[c].w * rinv;
            gatt4[j] = p;
            uint2 hv;
            hv.x = pack_h2(__float2half(p.x), __float2half(p.y));
            hv.y = pack_h2(__float2half(p.z), __float2half(p.w));
            *(uint2*)(sm3 + li * APAD + j * 8) = hv;
        }
    }

    // ---- Phase B: h_prime = att @ Wh_b, fp16 mma.sync ----
    const int wm = wid >> 1;           // 0..3: rows wm*16..wm*16+15
    const int wn = wid & 1;            // 0..1: cols wn*128..wn*128+127

    const int a_r = wm * 16 + (lane & 15);
    const uint32_t a_base = sb + (uint32_t)(a_r * APAD + (lane >> 4) * 16);
    const uint32_t b_off  = (uint32_t)((lane & 15) * BSTRIDE +
                                       (wn * 128 + (lane >> 4) * 8) * 2);

    float acc[16][4];
#pragma unroll
    for (int ni = 0; ni < 16; ni++)
#pragma unroll
        for (int q = 0; q < 4; q++) acc[ni][q] = 0.f;

    for (int c = 0; c < NCHK3; c++) {
        const int buf = c & 3;
        // Chunk c's copies complete (2 newer groups may remain in flight):
        if (c < NCHK3 - 2) { CP_WAIT2(); } else { CP_WAIT0(); }
        // Visibility of chunk c to all threads + chunk c-1 fully consumed:
        __syncthreads();
        // Stage chunk c+3 into the buffer chunk c-1 vacated.
        if (c + 3 < NCHK3) { stage_whf(sb, (c + 3) & 3, c + 3, b, tid); CP_COMMIT(); }

        uint32_t ah[4];
        LDSM_X4(ah, a_base + (uint32_t)(c * 32));          // c*16 elems * 2B

        const uint32_t bbase = sb + B_BASE + buf * BSTAGE + b_off;
#pragma unroll
        for (int g = 0; g < 8; g++) {
            uint32_t bh[4];
            LDSM_X4_T(bh, bbase + g * 32);                 // g*16 cols * 2B
            mma16816(acc[2 * g],     ah, bh[0], bh[1]);
            mma16816(acc[2 * g + 1], ah, bh[2], bh[3]);
        }
    }

    // Epilogue: write h_prime [64 x 256] tile.
    const int g = lane >> 2, t = lane & 3;
    const int rbase = b * NN + it * 64 + wm * 16;
#pragma unroll
    for (int h2 = 0; h2 < 2; h2++) {
        float* orow = &out_h[(size_t)(rbase + g + h2 * 8) * DOUT_];
#pragma unroll
        for (int ni = 0; ni < 16; ni++) {
            const int col = wn * 128 + ni * 8 + t * 2;
            float2 o;
            o.x = acc[ni][h2 * 2 + 0];
            o.y = acc[ni][h2 * 2 + 1];
            *(float2*)&orow[col] = o;
        }
    }
}

// ---------------------------------------------------------------------------
extern "C" void kernel_launch(void* const* d_in, const int* in_sizes, int n_in,
                              void* d_out, int out_size) {
    const float* h         = (const float*)d_in[0];
    const int*   adj       = (const int*)  d_in[1];
    const int*   positions = (const int*)  d_in[2];
    const float* W         = (const float*)d_in[3];
    const float* a1        = (const float*)d_in[4];
    const float* a2        = (const float*)d_in[5];
    const float* pos_table = (const float*)d_in[6];

    float* out_h   = (float*)d_out;                           // [32,512,256]
    float* out_att = (float*)d_out + (size_t)BB * NN * DOUT_; // [32,512,512]

    wt_convert_kernel<<<192, 256>>>(W);   // also zeroes g_s1/g_s2

    cudaFuncSetAttribute(gemm_wh_mma_kernel,
                         cudaFuncAttributeMaxDynamicSharedMemorySize, GSMEM);
    dim3 g1(DOUT_ / 128, MROWS / 128);   // (2, 128) = 256 CTAs
    gemm_wh_mma_kernel<<<g1, 256, GSMEM>>>(h, positions, pos_table, a1, a2);

    cudaFuncSetAttribute(attn_kernel,
                         cudaFuncAttributeMaxDynamicSharedMemorySize, SMEM3_T);
    attn_kernel<<<BB * 8, 256, SMEM3_T>>>(adj, out_h, out_att);
}